// round 7
// baseline (speedup 1.0000x reference)
#include <cuda_runtime.h>
#include <cuda_bf16.h>
#include <math.h>
#include <stdint.h>

#define N_NODES 100000
#define N_EDGES 1600000
#define DIM 128
#define SCAN_BLK 1024
#define NBLK ((N_NODES + SCAN_BLK - 1) / SCAN_BLK)   // 98

// ---------------- scratch (device globals; no allocations allowed) -------------
__device__ int   g_is64;
__device__ int   g_cnt[N_NODES];
__device__ int   g_cur[N_NODES];
__device__ int   g_tmp[N_NODES];
__device__ int   g_blocksum[128];
__device__ int   g_blockoff[128];
__device__ int   g_rowptr[N_NODES + 1];
__device__ int   g_perm[N_EDGES];
__device__ float g_deginv[N_NODES];
__device__ float g_h1[(size_t)N_NODES * DIM];
__device__ float g_h2[(size_t)N_NODES * DIM];
__device__ float g_wt1[128 * 256];
__device__ float g_wt2[128 * 256];
__device__ float g_p[N_NODES * 2];
__device__ float g_q[N_NODES * 2];

__device__ __forceinline__ float cvt_tf32(float x) {
    float r; asm("cvt.rna.tf32.f32 %0, %1;" : "=f"(r) : "f"(x)); return r;
}

// ---------------- dtype detection -------------------------------------------
__global__ void k_detect(const int* __restrict__ ei32) {
    __shared__ int nz;
    if (threadIdx.x == 0) nz = 0;
    __syncthreads();
    for (int i = threadIdx.x; i < 4096; i += blockDim.x)
        if (ei32[2 * i + 1] != 0) nz = 1;
    __syncthreads();
    if (threadIdx.x == 0) g_is64 = (nz == 0) ? 1 : 0;
}

__device__ __forceinline__ int load_idx(const void* ei, size_t pos, int is64) {
    if (is64) return (int)((const long long*)ei)[pos];
    return ((const int*)ei)[pos];
}

// ---------------- CSR build --------------------------------------------------
__global__ void k_zero_counts() {
    int i = blockIdx.x * blockDim.x + threadIdx.x;
    if (i < N_NODES) { g_cnt[i] = 0; g_cur[i] = 0; }
}

__global__ void k_hist(const void* __restrict__ ei) {
    int e = blockIdx.x * blockDim.x + threadIdx.x;
    int is64 = g_is64;
    if (e < N_EDGES) {
        int d = load_idx(ei, (size_t)N_EDGES + e, is64);
        atomicAdd(&g_cnt[d], 1);
    }
}

__global__ void k_scan_a() {
    __shared__ int sh[SCAN_BLK];
    int tid = threadIdx.x;
    int i = blockIdx.x * SCAN_BLK + tid;
    int v = (i < N_NODES) ? g_cnt[i] : 0;
    sh[tid] = v;
    __syncthreads();
    for (int off = 1; off < SCAN_BLK; off <<= 1) {
        int t = 0;
        if (tid >= off) t = sh[tid - off];
        __syncthreads();
        if (tid >= off) sh[tid] += t;
        __syncthreads();
    }
    if (i < N_NODES) g_tmp[i] = sh[tid] - v;
    if (tid == SCAN_BLK - 1) g_blocksum[blockIdx.x] = sh[tid];
}

__global__ void k_scan_b() {
    __shared__ int sh[128];
    int tid = threadIdx.x;
    int v = (tid < NBLK) ? g_blocksum[tid] : 0;
    sh[tid] = v;
    __syncthreads();
    for (int off = 1; off < 128; off <<= 1) {
        int t = 0;
        if (tid >= off) t = sh[tid - off];
        __syncthreads();
        if (tid >= off) sh[tid] += t;
        __syncthreads();
    }
    if (tid < NBLK) g_blockoff[tid] = sh[tid] - v;
}

__global__ void k_scan_c() {
    int i = blockIdx.x * SCAN_BLK + threadIdx.x;
    if (i < N_NODES) {
        g_rowptr[i] = g_tmp[i] + g_blockoff[blockIdx.x];
        int c = g_cnt[i];
        g_deginv[i] = 1.0f / (float)max(c, 1);
    }
    if (i == 0) g_rowptr[N_NODES] = N_EDGES;
}

__global__ void k_perm(const void* __restrict__ ei) {
    int e = blockIdx.x * blockDim.x + threadIdx.x;
    int is64 = g_is64;
    if (e < N_EDGES) {
        int s = load_idx(ei, (size_t)e, is64);
        int d = load_idx(ei, (size_t)N_EDGES + e, is64);
        int pos = g_rowptr[d] + atomicAdd(&g_cur[d], 1);
        g_perm[pos] = s;
    }
}

// ---------------- weight transpose + stack: Wt[n][k] k=0..255 -----------------
__global__ void k_wt(const float* __restrict__ Wl, const float* __restrict__ Wr,
                     float* __restrict__ Wt) {
    int idx = blockIdx.x * blockDim.x + threadIdx.x;
    if (idx < 128 * 128) {
        int k = idx >> 7, n = idx & 127;
        Wt[n * 256 + k]       = Wl[k * 128 + n];
        Wt[n * 256 + 128 + k] = Wr[k * 128 + n];
    }
}

// ---------------- fused layer: gather -> smem, then tf32 MMA ------------------
// CTA: 128 dst rows, 256 threads (8 warps). Sagg[128][132] tf32-converted
// aggregate; X half chunk-loaded; B (Wt) chunk-loaded. mma.m16n8k8.tf32.
#define FSTRIDE 132
#define CSTRIDE 36
#define SM_FLOATS (128 * FSTRIDE + 2 * 128 * CSTRIDE + 128)
#define SM_BYTES (SM_FLOATS * 4)

__device__ __forceinline__ void mma_tf32(float* c, uint32_t a0, uint32_t a1,
                                         uint32_t a2, uint32_t a3,
                                         uint32_t b0, uint32_t b1) {
    asm volatile(
        "mma.sync.aligned.m16n8k8.row.col.f32.tf32.tf32.f32 "
        "{%0,%1,%2,%3}, {%4,%5,%6,%7}, {%8,%9}, {%0,%1,%2,%3};"
        : "+f"(c[0]), "+f"(c[1]), "+f"(c[2]), "+f"(c[3])
        : "r"(a0), "r"(a1), "r"(a2), "r"(a3), "r"(b0), "r"(b1));
}

__global__ void __launch_bounds__(256, 2)
k_layer(const float* __restrict__ feat, const float* __restrict__ Wt,
        const float* __restrict__ bias, float* __restrict__ out) {
    extern __shared__ float sm[];
    float* Sagg  = sm;                          // 128*132
    float* Xs    = Sagg + 128 * FSTRIDE;        // 128*36
    float* Bs    = Xs + 128 * CSTRIDE;          // 128*36
    float* sbias = Bs + 128 * CSTRIDE;          // 128

    int tid = threadIdx.x;
    int wid = tid >> 5, lane = tid & 31;
    int g = lane >> 2, t = lane & 3;
    int warp_m = (wid >> 2) * 64;
    int warp_n = (wid & 3) * 32;
    int row_base = blockIdx.x * 128;

    if (tid < 128) sbias[tid] = bias[tid];

    // ---- Phase A: gather (warp per node, 16 nodes per warp) ----
#pragma unroll 1
    for (int i = 0; i < 16; i++) {
        int row = wid * 16 + i;
        int node = row_base + row;
        float4 acc = make_float4(0.f, 0.f, 0.f, 0.f);
        if (node < N_NODES) {
            int s0 = g_rowptr[node];
            int s1 = g_rowptr[node + 1];
            int e = s0;
            for (; e + 3 < s1; e += 4) {
                int sa = __ldg(&g_perm[e]);
                int sb = __ldg(&g_perm[e + 1]);
                int sc = __ldg(&g_perm[e + 2]);
                int sd = __ldg(&g_perm[e + 3]);
                float4 va = *(const float4*)(feat + (size_t)sa * DIM + lane * 4);
                float4 vb = *(const float4*)(feat + (size_t)sb * DIM + lane * 4);
                float4 vc = *(const float4*)(feat + (size_t)sc * DIM + lane * 4);
                float4 vd = *(const float4*)(feat + (size_t)sd * DIM + lane * 4);
                acc.x += (va.x + vb.x) + (vc.x + vd.x);
                acc.y += (va.y + vb.y) + (vc.y + vd.y);
                acc.z += (va.z + vb.z) + (vc.z + vd.z);
                acc.w += (va.w + vb.w) + (vc.w + vd.w);
            }
            for (; e < s1; e++) {
                int sa = __ldg(&g_perm[e]);
                float4 va = *(const float4*)(feat + (size_t)sa * DIM + lane * 4);
                acc.x += va.x; acc.y += va.y; acc.z += va.z; acc.w += va.w;
            }
            float di = g_deginv[node];
            acc.x *= di; acc.y *= di; acc.z *= di; acc.w *= di;
        }
        float4 o;
        o.x = cvt_tf32(acc.x); o.y = cvt_tf32(acc.y);
        o.z = cvt_tf32(acc.z); o.w = cvt_tf32(acc.w);
        *(float4*)(Sagg + row * FSTRIDE + lane * 4) = o;
    }

    // ---- Phase B: MMA over K=256 (0..127 from Sagg, 128..255 from feat) ----
    float acc[4][4][4];
#pragma unroll
    for (int i = 0; i < 4; i++)
#pragma unroll
        for (int j = 0; j < 4; j++)
#pragma unroll
            for (int q = 0; q < 4; q++) acc[i][j][q] = 0.f;

    for (int ch = 0; ch < 8; ch++) {
        int k0 = ch * 32;
        __syncthreads();   // also serves as Phase A barrier at ch=0
        // load B chunk: 128 n-rows x 32 k
#pragma unroll
        for (int i = 0; i < 4; i++) {
            int f = tid + i * 256;
            int row = f >> 3, seg = f & 7;
            float4 v = *(const float4*)(Wt + (size_t)row * 256 + k0 + seg * 4);
            v.x = cvt_tf32(v.x); v.y = cvt_tf32(v.y);
            v.z = cvt_tf32(v.z); v.w = cvt_tf32(v.w);
            *(float4*)(Bs + row * CSTRIDE + seg * 4) = v;
        }
        // load X chunk for K>=128
        if (ch >= 4) {
            int kbase = k0 - 128;
#pragma unroll
            for (int i = 0; i < 4; i++) {
                int f = tid + i * 256;
                int row = f >> 3, seg = f & 7;
                float4 v = make_float4(0.f, 0.f, 0.f, 0.f);
                int gr = row_base + row;
                if (gr < N_NODES)
                    v = *(const float4*)(feat + (size_t)gr * DIM + kbase + seg * 4);
                v.x = cvt_tf32(v.x); v.y = cvt_tf32(v.y);
                v.z = cvt_tf32(v.z); v.w = cvt_tf32(v.w);
                *(float4*)(Xs + row * CSTRIDE + seg * 4) = v;
            }
        }
        __syncthreads();

        const float* Asm = (ch < 4) ? Sagg : Xs;
        int astr = (ch < 4) ? FSTRIDE : CSTRIDE;
        int abase = (ch < 4) ? k0 : 0;

#pragma unroll
        for (int kk = 0; kk < 4; kk++) {
            int kofA = abase + kk * 8;
            int kofB = kk * 8;
            uint32_t af[4][4];
#pragma unroll
            for (int mi = 0; mi < 4; mi++) {
                const float* ap = Asm + (warp_m + mi * 16 + g) * astr + kofA + t;
                af[mi][0] = __float_as_uint(ap[0]);
                af[mi][1] = __float_as_uint(ap[8 * astr]);
                af[mi][2] = __float_as_uint(ap[4]);
                af[mi][3] = __float_as_uint(ap[8 * astr + 4]);
            }
            uint32_t bf[4][2];
#pragma unroll
            for (int ni = 0; ni < 4; ni++) {
                const float* bp = Bs + (warp_n + ni * 8 + g) * CSTRIDE + kofB + t;
                bf[ni][0] = __float_as_uint(bp[0]);
                bf[ni][1] = __float_as_uint(bp[4]);
            }
#pragma unroll
            for (int mi = 0; mi < 4; mi++)
#pragma unroll
                for (int ni = 0; ni < 4; ni++)
                    mma_tf32(acc[mi][ni], af[mi][0], af[mi][1], af[mi][2], af[mi][3],
                             bf[ni][0], bf[ni][1]);
        }
    }

    // epilogue: bias + relu, direct stores
#pragma unroll
    for (int mi = 0; mi < 4; mi++) {
        int r0 = row_base + warp_m + mi * 16 + g;
        int r1 = r0 + 8;
#pragma unroll
        for (int ni = 0; ni < 4; ni++) {
            int c0 = warp_n + ni * 8 + t * 2;
            float b0 = sbias[c0], b1 = sbias[c0 + 1];
            if (r0 < N_NODES) {
                float2 v = make_float2(fmaxf(acc[mi][ni][0] + b0, 0.f),
                                       fmaxf(acc[mi][ni][1] + b1, 0.f));
                *(float2*)(out + (size_t)r0 * DIM + c0) = v;
            }
            if (r1 < N_NODES) {
                float2 v = make_float2(fmaxf(acc[mi][ni][2] + b0, 0.f),
                                       fmaxf(acc[mi][ni][3] + b1, 0.f));
                *(float2*)(out + (size_t)r1 * DIM + c0) = v;
            }
        }
    }
}

// ---------------- layer-3 pre-projection: p = h2@W3_l, q = h2@W3_r + b3 ------
__global__ void k_pq(const float* __restrict__ W3l, const float* __restrict__ W3r,
                     const float* __restrict__ b3) {
    int warp = (blockIdx.x * blockDim.x + threadIdx.x) >> 5;
    int lane = threadIdx.x & 31;
    if (warp >= N_NODES) return;
    float4 h = *(const float4*)(g_h2 + (size_t)warp * DIM + lane * 4);
    float hv[4] = {h.x, h.y, h.z, h.w};
    float pl0 = 0.f, pl1 = 0.f, pr0 = 0.f, pr1 = 0.f;
#pragma unroll
    for (int j = 0; j < 4; j++) {
        int k = lane * 4 + j;
        pl0 = fmaf(hv[j], __ldg(&W3l[k * 2 + 0]), pl0);
        pl1 = fmaf(hv[j], __ldg(&W3l[k * 2 + 1]), pl1);
        pr0 = fmaf(hv[j], __ldg(&W3r[k * 2 + 0]), pr0);
        pr1 = fmaf(hv[j], __ldg(&W3r[k * 2 + 1]), pr1);
    }
#pragma unroll
    for (int off = 16; off > 0; off >>= 1) {
        pl0 += __shfl_down_sync(0xffffffffu, pl0, off);
        pl1 += __shfl_down_sync(0xffffffffu, pl1, off);
        pr0 += __shfl_down_sync(0xffffffffu, pr0, off);
        pr1 += __shfl_down_sync(0xffffffffu, pr1, off);
    }
    if (lane == 0) {
        g_p[warp * 2 + 0] = pl0;
        g_p[warp * 2 + 1] = pl1;
        g_q[warp * 2 + 0] = pr0 + b3[0];
        g_q[warp * 2 + 1] = pr1 + b3[1];
    }
}

// ---------------- layer-3 gather + relu + log_softmax ------------------------
__global__ void k_final(float* __restrict__ out) {
    int warp = (blockIdx.x * blockDim.x + threadIdx.x) >> 5;
    int lane = threadIdx.x & 31;
    if (warp >= N_NODES) return;
    int s0 = g_rowptr[warp];
    int s1 = g_rowptr[warp + 1];
    float a0 = 0.f, a1 = 0.f;
    for (int e = s0 + lane; e < s1; e += 32) {
        int s = __ldg(&g_perm[e]);
        a0 += g_p[s * 2 + 0];
        a1 += g_p[s * 2 + 1];
    }
#pragma unroll
    for (int off = 16; off > 0; off >>= 1) {
        a0 += __shfl_down_sync(0xffffffffu, a0, off);
        a1 += __shfl_down_sync(0xffffffffu, a1, off);
    }
    if (lane == 0) {
        float di = g_deginv[warp];
        float v0 = fmaxf(a0 * di + g_q[warp * 2 + 0], 0.f);
        float v1 = fmaxf(a1 * di + g_q[warp * 2 + 1], 0.f);
        float m = fmaxf(v0, v1);
        float lse = m + logf(expf(v0 - m) + expf(v1 - m));
        out[warp * 2 + 0] = v0 - lse;
        out[warp * 2 + 1] = v1 - lse;
    }
}

// ---------------- launch -----------------------------------------------------
extern "C" void kernel_launch(void* const* d_in, const int* in_sizes, int n_in,
                              void* d_out, int out_size) {
    const float* x   = (const float*)d_in[0];
    const void*  ei  = d_in[1];
    const float* W1l = (const float*)d_in[2];
    const float* W1r = (const float*)d_in[3];
    const float* b1  = (const float*)d_in[4];
    const float* W2l = (const float*)d_in[5];
    const float* W2r = (const float*)d_in[6];
    const float* b2  = (const float*)d_in[7];
    const float* W3l = (const float*)d_in[8];
    const float* W3r = (const float*)d_in[9];
    const float* b3  = (const float*)d_in[10];
    float* out = (float*)d_out;

    const int EDGE_BLOCKS = (N_EDGES + 255) / 256;
    const int NODE_BLOCKS = (N_NODES + 255) / 256;
    const int WARP_BLOCKS = (N_NODES * 32 + 255) / 256;
    const int TILE_BLOCKS = (N_NODES + 127) / 128;     // 782

    float* h1;  cudaGetSymbolAddress((void**)&h1,  g_h1);
    float* h2;  cudaGetSymbolAddress((void**)&h2,  g_h2);
    float* wt1; cudaGetSymbolAddress((void**)&wt1, g_wt1);
    float* wt2; cudaGetSymbolAddress((void**)&wt2, g_wt2);

    cudaFuncSetAttribute(k_layer, cudaFuncAttributeMaxDynamicSharedMemorySize, SM_BYTES);

    // dtype sniff + CSR build + weight prep
    k_detect<<<1, 256>>>((const int*)ei);
    k_zero_counts<<<NODE_BLOCKS, 256>>>();
    k_hist<<<EDGE_BLOCKS, 256>>>(ei);
    k_scan_a<<<NBLK, SCAN_BLK>>>();
    k_scan_b<<<1, 128>>>();
    k_scan_c<<<NBLK, SCAN_BLK>>>();
    k_perm<<<EDGE_BLOCKS, 256>>>(ei);
    k_wt<<<(128 * 128 + 255) / 256, 256>>>(W1l, W1r, wt1);
    k_wt<<<(128 * 128 + 255) / 256, 256>>>(W2l, W2r, wt2);

    // layers 1 & 2 (fused gather + GEMM)
    k_layer<<<TILE_BLOCKS, 256, SM_BYTES>>>(x,  wt1, b1, h1);
    k_layer<<<TILE_BLOCKS, 256, SM_BYTES>>>(h1, wt2, b2, h2);

    // layer 3 (projection first, then 2-wide aggregation)
    k_pq<<<WARP_BLOCKS, 256>>>(W3l, W3r, b3);
    k_final<<<WARP_BLOCKS, 256>>>(out);
}

// round 8
// speedup vs baseline: 1.4420x; 1.4420x over previous
#include <cuda_runtime.h>
#include <cuda_bf16.h>
#include <math.h>
#include <stdint.h>

#define N_NODES 100000
#define N_EDGES 1600000
#define DIM 128
#define SCAN_BLK 1024
#define NBLK ((N_NODES + SCAN_BLK - 1) / SCAN_BLK)   // 98

// ---------------- scratch (device globals; no allocations allowed) -------------
__device__ int   g_is64;
__device__ int   g_cnt[N_NODES];
__device__ int   g_cur[N_NODES];
__device__ int   g_tmp[N_NODES];
__device__ int   g_blocksum[128];
__device__ int   g_blockoff[128];
__device__ int   g_rowptr[N_NODES + 1];
__device__ int   g_perm[N_EDGES];
__device__ float g_deginv[N_NODES];
__device__ float g_agg[(size_t)N_NODES * DIM];
__device__ float g_h1[(size_t)N_NODES * DIM];
__device__ float g_h2[(size_t)N_NODES * DIM];
__device__ float g_wt1[128 * 256];
__device__ float g_wt2[128 * 256];
__device__ float g_p[N_NODES * 2];
__device__ float g_q[N_NODES * 2];

__device__ __forceinline__ float cvt_tf32(float x) {
    float r; asm("cvt.rna.tf32.f32 %0, %1;" : "=f"(r) : "f"(x)); return r;
}

__device__ __forceinline__ int load_idx(const void* ei, size_t pos, int is64) {
    if (is64) return (int)((const long long*)ei)[pos];
    return ((const int*)ei)[pos];
}

// ---------------- CSR build --------------------------------------------------
// block 0 also sniffs the edge_index dtype (int64 stores -> odd words all 0)
__global__ void k_zero_counts(const int* __restrict__ ei32) {
    int i = blockIdx.x * blockDim.x + threadIdx.x;
    if (i < N_NODES) { g_cnt[i] = 0; g_cur[i] = 0; }
    if (blockIdx.x == 0) {
        __shared__ int nz;
        if (threadIdx.x == 0) nz = 0;
        __syncthreads();
        for (int j = threadIdx.x; j < 4096; j += blockDim.x)
            if (ei32[2 * j + 1] != 0) nz = 1;
        __syncthreads();
        if (threadIdx.x == 0) g_is64 = (nz == 0) ? 1 : 0;
    }
}

__global__ void k_hist(const void* __restrict__ ei) {
    int e = blockIdx.x * blockDim.x + threadIdx.x;
    int is64 = g_is64;
    if (e < N_EDGES) {
        int d = load_idx(ei, (size_t)N_EDGES + e, is64);
        atomicAdd(&g_cnt[d], 1);
    }
}

__global__ void k_scan_a() {
    __shared__ int sh[SCAN_BLK];
    int tid = threadIdx.x;
    int i = blockIdx.x * SCAN_BLK + tid;
    int v = (i < N_NODES) ? g_cnt[i] : 0;
    sh[tid] = v;
    __syncthreads();
    for (int off = 1; off < SCAN_BLK; off <<= 1) {
        int t = 0;
        if (tid >= off) t = sh[tid - off];
        __syncthreads();
        if (tid >= off) sh[tid] += t;
        __syncthreads();
    }
    if (i < N_NODES) g_tmp[i] = sh[tid] - v;
    if (tid == SCAN_BLK - 1) g_blocksum[blockIdx.x] = sh[tid];
}

__global__ void k_scan_b() {
    __shared__ int sh[128];
    int tid = threadIdx.x;
    int v = (tid < NBLK) ? g_blocksum[tid] : 0;
    sh[tid] = v;
    __syncthreads();
    for (int off = 1; off < 128; off <<= 1) {
        int t = 0;
        if (tid >= off) t = sh[tid - off];
        __syncthreads();
        if (tid >= off) sh[tid] += t;
        __syncthreads();
    }
    if (tid < NBLK) g_blockoff[tid] = sh[tid] - v;
}

__global__ void k_scan_c() {
    int i = blockIdx.x * SCAN_BLK + threadIdx.x;
    if (i < N_NODES) {
        g_rowptr[i] = g_tmp[i] + g_blockoff[blockIdx.x];
        int c = g_cnt[i];
        g_deginv[i] = 1.0f / (float)max(c, 1);
    }
    if (i == 0) g_rowptr[N_NODES] = N_EDGES;
}

__global__ void k_perm(const void* __restrict__ ei) {
    int e = blockIdx.x * blockDim.x + threadIdx.x;
    int is64 = g_is64;
    if (e < N_EDGES) {
        int s = load_idx(ei, (size_t)e, is64);
        int d = load_idx(ei, (size_t)N_EDGES + e, is64);
        int pos = g_rowptr[d] + atomicAdd(&g_cur[d], 1);
        g_perm[pos] = s;
    }
}

// ---------------- weight transpose + stack (tf32 pre-rounded) -----------------
__global__ void k_wt(const float* __restrict__ Wl, const float* __restrict__ Wr,
                     float* __restrict__ Wt) {
    int idx = blockIdx.x * blockDim.x + threadIdx.x;
    if (idx < 128 * 128) {
        int k = idx >> 7, n = idx & 127;
        Wt[n * 256 + k]       = cvt_tf32(Wl[k * 128 + n]);
        Wt[n * 256 + 128 + k] = cvt_tf32(Wr[k * 128 + n]);
    }
}

// ---------------- gather-aggregate (warp per node, lane owns 4 feats) --------
// output pre-rounded to tf32 (rna) — consumed only by the MMA.
__global__ void k_gather(const float* __restrict__ feat, float* __restrict__ out) {
    int warp = (blockIdx.x * blockDim.x + threadIdx.x) >> 5;
    int lane = threadIdx.x & 31;
    if (warp >= N_NODES) return;
    int s0 = g_rowptr[warp];
    int s1 = g_rowptr[warp + 1];
    float4 acc = make_float4(0.f, 0.f, 0.f, 0.f);
    int e = s0;
    for (; e + 1 < s1; e += 2) {
        int sa = __ldg(&g_perm[e]);
        int sb = __ldg(&g_perm[e + 1]);
        float4 va = *(const float4*)(feat + (size_t)sa * DIM + lane * 4);
        float4 vb = *(const float4*)(feat + (size_t)sb * DIM + lane * 4);
        acc.x += va.x; acc.y += va.y; acc.z += va.z; acc.w += va.w;
        acc.x += vb.x; acc.y += vb.y; acc.z += vb.z; acc.w += vb.w;
    }
    if (e < s1) {
        int sa = __ldg(&g_perm[e]);
        float4 va = *(const float4*)(feat + (size_t)sa * DIM + lane * 4);
        acc.x += va.x; acc.y += va.y; acc.z += va.z; acc.w += va.w;
    }
    float di = g_deginv[warp];
    float4 o;
    o.x = cvt_tf32(acc.x * di); o.y = cvt_tf32(acc.y * di);
    o.z = cvt_tf32(acc.z * di); o.w = cvt_tf32(acc.w * di);
    *(float4*)(out + (size_t)warp * DIM + lane * 4) = o;
}

// ---------------- tf32 mma.sync GEMM with cp.async double buffering ----------
// CTA: 128(M) x 128(N). 8 warps 2x4, warp tile 64x32. K=256, 8 chunks of 32.
#define ASTRIDE 36
#define BUF_FLOATS (128 * ASTRIDE)                 // 4608 floats / 18.4KB
#define GSM_FLOATS (4 * BUF_FLOATS + 128)
#define GSM_BYTES (GSM_FLOATS * 4)

__device__ __forceinline__ void cp16(uint32_t dst, const void* src, uint32_t srcsz) {
    asm volatile("cp.async.ca.shared.global [%0], [%1], 16, %2;"
                 :: "r"(dst), "l"(src), "r"(srcsz) : "memory");
}
__device__ __forceinline__ void cp_commit() {
    asm volatile("cp.async.commit_group;" ::: "memory");
}
template <int N>
__device__ __forceinline__ void cp_wait() {
    asm volatile("cp.async.wait_group %0;" :: "n"(N) : "memory");
}

__device__ __forceinline__ void mma_tf32(float* c, uint32_t a0, uint32_t a1,
                                         uint32_t a2, uint32_t a3,
                                         uint32_t b0, uint32_t b1) {
    asm volatile(
        "mma.sync.aligned.m16n8k8.row.col.f32.tf32.tf32.f32 "
        "{%0,%1,%2,%3}, {%4,%5,%6,%7}, {%8,%9}, {%0,%1,%2,%3};"
        : "+f"(c[0]), "+f"(c[1]), "+f"(c[2]), "+f"(c[3])
        : "r"(a0), "r"(a1), "r"(a2), "r"(a3), "r"(b0), "r"(b1));
}

__global__ void __launch_bounds__(256, 2)
k_gemm_mma(const float* __restrict__ Aagg, const float* __restrict__ Ax,
           const float* __restrict__ Wt, const float* __restrict__ bias,
           float* __restrict__ out) {
    extern __shared__ float sm[];
    float* Abuf = sm;                       // 2 x 128*36
    float* Bbuf = sm + 2 * BUF_FLOATS;      // 2 x 128*36
    float* sbias = sm + 4 * BUF_FLOATS;     // 128

    int tid = threadIdx.x;
    int wid = tid >> 5, lane = tid & 31;
    int g = lane >> 2, t = lane & 3;
    int warp_m = (wid >> 2) * 64;
    int warp_n = (wid & 3) * 32;
    int row_base = blockIdx.x * 128;

    if (tid < 128) sbias[tid] = bias[tid];

    uint32_t a_sm_base = (uint32_t)__cvta_generic_to_shared(Abuf);
    uint32_t b_sm_base = (uint32_t)__cvta_generic_to_shared(Bbuf);

    // per-thread load coordinates (same for every chunk)
    int lrow[4], lseg[4];
#pragma unroll
    for (int i = 0; i < 4; i++) {
        int f = tid + i * 256;
        lrow[i] = f >> 3;
        lseg[i] = f & 7;
    }

    // issue chunk loads into buffer s
    auto issue = [&](int ch, int s) {
        int k0 = ch * 32;
        const float* Asrc = (k0 < 128) ? Aagg : Ax;
        int kbase = k0 & 127;
        uint32_t ao = a_sm_base + (uint32_t)(s * BUF_FLOATS * 4);
        uint32_t bo = b_sm_base + (uint32_t)(s * BUF_FLOATS * 4);
#pragma unroll
        for (int i = 0; i < 4; i++) {
            int row = lrow[i], seg = lseg[i];
            int gr = row_base + row;
            int ok = gr < N_NODES;
            const float* src = Asrc + (size_t)(ok ? gr : 0) * DIM + kbase + seg * 4;
            cp16(ao + (uint32_t)((row * ASTRIDE + seg * 4) * 4), src, ok ? 16u : 0u);
        }
#pragma unroll
        for (int i = 0; i < 4; i++) {
            int row = lrow[i], seg = lseg[i];
            const float* src = Wt + (size_t)row * 256 + k0 + seg * 4;
            cp16(bo + (uint32_t)((row * ASTRIDE + seg * 4) * 4), src, 16u);
        }
        cp_commit();
    };

    float acc[4][4][4];
#pragma unroll
    for (int i = 0; i < 4; i++)
#pragma unroll
        for (int j = 0; j < 4; j++)
#pragma unroll
            for (int q = 0; q < 4; q++) acc[i][j][q] = 0.f;

    issue(0, 0);

    for (int ch = 0; ch < 8; ch++) {
        int s = ch & 1;
        if (ch < 7) issue(ch + 1, s ^ 1);
        if (ch < 7) cp_wait<1>(); else cp_wait<0>();
        __syncthreads();

        const float* As = Abuf + s * BUF_FLOATS;
        const float* Bs = Bbuf + s * BUF_FLOATS;
#pragma unroll
        for (int kk = 0; kk < 4; kk++) {
            int kof = kk * 8;
            uint32_t af[4][4];
#pragma unroll
            for (int mi = 0; mi < 4; mi++) {
                const float* ap = As + (warp_m + mi * 16 + g) * ASTRIDE + kof + t;
                af[mi][0] = __float_as_uint(ap[0]);
                af[mi][1] = __float_as_uint(ap[8 * ASTRIDE]);
                af[mi][2] = __float_as_uint(ap[4]);
                af[mi][3] = __float_as_uint(ap[8 * ASTRIDE + 4]);
            }
            uint32_t bf[4][2];
#pragma unroll
            for (int ni = 0; ni < 4; ni++) {
                const float* bp = Bs + (warp_n + ni * 8 + g) * ASTRIDE + kof + t;
                bf[ni][0] = __float_as_uint(bp[0]);
                bf[ni][1] = __float_as_uint(bp[4]);
            }
#pragma unroll
            for (int mi = 0; mi < 4; mi++)
#pragma unroll
                for (int ni = 0; ni < 4; ni++)
                    mma_tf32(acc[mi][ni], af[mi][0], af[mi][1], af[mi][2], af[mi][3],
                             bf[ni][0], bf[ni][1]);
        }
        __syncthreads();
    }

    // epilogue: bias + relu, direct stores
#pragma unroll
    for (int mi = 0; mi < 4; mi++) {
        int r0 = row_base + warp_m + mi * 16 + g;
        int r1 = r0 + 8;
#pragma unroll
        for (int ni = 0; ni < 4; ni++) {
            int c0 = warp_n + ni * 8 + t * 2;
            float b0 = sbias[c0], b1 = sbias[c0 + 1];
            if (r0 < N_NODES) {
                float2 v = make_float2(fmaxf(acc[mi][ni][0] + b0, 0.f),
                                       fmaxf(acc[mi][ni][1] + b1, 0.f));
                *(float2*)(out + (size_t)r0 * DIM + c0) = v;
            }
            if (r1 < N_NODES) {
                float2 v = make_float2(fmaxf(acc[mi][ni][2] + b0, 0.f),
                                       fmaxf(acc[mi][ni][3] + b1, 0.f));
                *(float2*)(out + (size_t)r1 * DIM + c0) = v;
            }
        }
    }
}

// ---------------- layer-3 pre-projection: p = h2@W3_l, q = h2@W3_r + b3 ------
__global__ void k_pq(const float* __restrict__ W3l, const float* __restrict__ W3r,
                     const float* __restrict__ b3) {
    int warp = (blockIdx.x * blockDim.x + threadIdx.x) >> 5;
    int lane = threadIdx.x & 31;
    if (warp >= N_NODES) return;
    float4 h = *(const float4*)(g_h2 + (size_t)warp * DIM + lane * 4);
    float hv[4] = {h.x, h.y, h.z, h.w};
    float pl0 = 0.f, pl1 = 0.f, pr0 = 0.f, pr1 = 0.f;
#pragma unroll
    for (int j = 0; j < 4; j++) {
        int k = lane * 4 + j;
        pl0 = fmaf(hv[j], __ldg(&W3l[k * 2 + 0]), pl0);
        pl1 = fmaf(hv[j], __ldg(&W3l[k * 2 + 1]), pl1);
        pr0 = fmaf(hv[j], __ldg(&W3r[k * 2 + 0]), pr0);
        pr1 = fmaf(hv[j], __ldg(&W3r[k * 2 + 1]), pr1);
    }
#pragma unroll
    for (int off = 16; off > 0; off >>= 1) {
        pl0 += __shfl_down_sync(0xffffffffu, pl0, off);
        pl1 += __shfl_down_sync(0xffffffffu, pl1, off);
        pr0 += __shfl_down_sync(0xffffffffu, pr0, off);
        pr1 += __shfl_down_sync(0xffffffffu, pr1, off);
    }
    if (lane == 0) {
        g_p[warp * 2 + 0] = pl0;
        g_p[warp * 2 + 1] = pl1;
        g_q[warp * 2 + 0] = pr0 + b3[0];
        g_q[warp * 2 + 1] = pr1 + b3[1];
    }
}

// ---------------- layer-3 gather + relu + log_softmax ------------------------
__global__ void k_final(float* __restrict__ out) {
    int warp = (blockIdx.x * blockDim.x + threadIdx.x) >> 5;
    int lane = threadIdx.x & 31;
    if (warp >= N_NODES) return;
    int s0 = g_rowptr[warp];
    int s1 = g_rowptr[warp + 1];
    float a0 = 0.f, a1 = 0.f;
    for (int e = s0 + lane; e < s1; e += 32) {
        int s = __ldg(&g_perm[e]);
        a0 += g_p[s * 2 + 0];
        a1 += g_p[s * 2 + 1];
    }
#pragma unroll
    for (int off = 16; off > 0; off >>= 1) {
        a0 += __shfl_down_sync(0xffffffffu, a0, off);
        a1 += __shfl_down_sync(0xffffffffu, a1, off);
    }
    if (lane == 0) {
        float di = g_deginv[warp];
        float v0 = fmaxf(a0 * di + g_q[warp * 2 + 0], 0.f);
        float v1 = fmaxf(a1 * di + g_q[warp * 2 + 1], 0.f);
        float m = fmaxf(v0, v1);
        float lse = m + logf(expf(v0 - m) + expf(v1 - m));
        out[warp * 2 + 0] = v0 - lse;
        out[warp * 2 + 1] = v1 - lse;
    }
}

// ---------------- launch -----------------------------------------------------
extern "C" void kernel_launch(void* const* d_in, const int* in_sizes, int n_in,
                              void* d_out, int out_size) {
    const float* x   = (const float*)d_in[0];
    const void*  ei  = d_in[1];
    const float* W1l = (const float*)d_in[2];
    const float* W1r = (const float*)d_in[3];
    const float* b1  = (const float*)d_in[4];
    const float* W2l = (const float*)d_in[5];
    const float* W2r = (const float*)d_in[6];
    const float* b2  = (const float*)d_in[7];
    const float* W3l = (const float*)d_in[8];
    const float* W3r = (const float*)d_in[9];
    const float* b3  = (const float*)d_in[10];
    float* out = (float*)d_out;

    const int EDGE_BLOCKS = (N_EDGES + 255) / 256;
    const int NODE_BLOCKS = (N_NODES + 255) / 256;
    const int WARP_BLOCKS = (N_NODES * 32 + 255) / 256;
    const int GEMM_BLOCKS = (N_NODES + 127) / 128;     // 782

    float* agg; cudaGetSymbolAddress((void**)&agg, g_agg);
    float* h1;  cudaGetSymbolAddress((void**)&h1,  g_h1);
    float* h2;  cudaGetSymbolAddress((void**)&h2,  g_h2);
    float* wt1; cudaGetSymbolAddress((void**)&wt1, g_wt1);
    float* wt2; cudaGetSymbolAddress((void**)&wt2, g_wt2);

    cudaFuncSetAttribute(k_gemm_mma, cudaFuncAttributeMaxDynamicSharedMemorySize, GSM_BYTES);

    // CSR build (block 0 of k_zero_counts sniffs dtype) + weight prep
    k_zero_counts<<<NODE_BLOCKS, 256>>>((const int*)ei);
    k_hist<<<EDGE_BLOCKS, 256>>>(ei);
    k_scan_a<<<NBLK, SCAN_BLK>>>();
    k_scan_b<<<1, 128>>>();
    k_scan_c<<<NBLK, SCAN_BLK>>>();
    k_perm<<<EDGE_BLOCKS, 256>>>(ei);
    k_wt<<<(128 * 128 + 255) / 256, 256>>>(W1l, W1r, wt1);
    k_wt<<<(128 * 128 + 255) / 256, 256>>>(W2l, W2r, wt2);

    // layer 1
    k_gather<<<WARP_BLOCKS, 256>>>(x, agg);
    k_gemm_mma<<<GEMM_BLOCKS, 256, GSM_BYTES>>>(agg, x, wt1, b1, h1);

    // layer 2
    k_gather<<<WARP_BLOCKS, 256>>>(h1, agg);
    k_gemm_mma<<<GEMM_BLOCKS, 256, GSM_BYTES>>>(agg, h1, wt2, b2, h2);

    // layer 3 (projection first, then 2-wide aggregation)
    k_pq<<<WARP_BLOCKS, 256>>>(W3l, W3r, b3);
    k_final<<<WARP_BLOCKS, 256>>>(out);
}

// round 10
// speedup vs baseline: 1.7153x; 1.1895x over previous
#include <cuda_runtime.h>
#include <cuda_bf16.h>
#include <math.h>
#include <stdint.h>

#define N_NODES 100000
#define N_EDGES 1600000
#define DIM 128
#define SCAN_BLK 1024
#define NBLK ((N_NODES + SCAN_BLK - 1) / SCAN_BLK)   // 98

// ---------------- scratch (device globals; no allocations allowed) -------------
__device__ int   g_is64;
__device__ int   g_cnt[N_NODES];
__device__ int   g_cur[N_NODES];
__device__ int   g_tmp[N_NODES];
__device__ int   g_blocksum[128];
__device__ int   g_blockoff[128];
__device__ int   g_rowptr[N_NODES + 1];
__device__ int   g_perm[N_EDGES];
__device__ float g_deginv[N_NODES];
__device__ float g_agg[(size_t)N_NODES * DIM];
__device__ float g_h1[(size_t)N_NODES * DIM];
__device__ float g_wt1[128 * 256];
__device__ float g_wt2[128 * 256];
__device__ float g_p[N_NODES * 2];
__device__ float g_q[N_NODES * 2];

__device__ __forceinline__ float cvt_tf32(float x) {
    float r; asm("cvt.rna.tf32.f32 %0, %1;" : "=f"(r) : "f"(x)); return r;
}

__device__ __forceinline__ int load_idx(const void* ei, size_t pos, int is64) {
    if (is64) return (int)((const long long*)ei)[pos];
    return ((const int*)ei)[pos];
}

// ---------------- CSR build --------------------------------------------------
// block 0 also sniffs the edge_index dtype (int64 stores -> odd words all 0)
__global__ void k_zero_counts(const int* __restrict__ ei32) {
    int i = blockIdx.x * blockDim.x + threadIdx.x;
    if (i < N_NODES) { g_cnt[i] = 0; g_cur[i] = 0; }
    if (blockIdx.x == 0) {
        __shared__ int nz;
        if (threadIdx.x == 0) nz = 0;
        __syncthreads();
        for (int j = threadIdx.x; j < 4096; j += blockDim.x)
            if (ei32[2 * j + 1] != 0) nz = 1;
        __syncthreads();
        if (threadIdx.x == 0) g_is64 = (nz == 0) ? 1 : 0;
    }
}

__global__ void k_hist(const void* __restrict__ ei) {
    int e = blockIdx.x * blockDim.x + threadIdx.x;
    int is64 = g_is64;
    if (e < N_EDGES) {
        int d = load_idx(ei, (size_t)N_EDGES + e, is64);
        atomicAdd(&g_cnt[d], 1);
    }
}

__global__ void k_scan_a() {
    __shared__ int sh[SCAN_BLK];
    int tid = threadIdx.x;
    int i = blockIdx.x * SCAN_BLK + tid;
    int v = (i < N_NODES) ? g_cnt[i] : 0;
    sh[tid] = v;
    __syncthreads();
    for (int off = 1; off < SCAN_BLK; off <<= 1) {
        int t = 0;
        if (tid >= off) t = sh[tid - off];
        __syncthreads();
        if (tid >= off) sh[tid] += t;
        __syncthreads();
    }
    if (i < N_NODES) g_tmp[i] = sh[tid] - v;
    if (tid == SCAN_BLK - 1) g_blocksum[blockIdx.x] = sh[tid];
}

__global__ void k_scan_b() {
    __shared__ int sh[128];
    int tid = threadIdx.x;
    int v = (tid < NBLK) ? g_blocksum[tid] : 0;
    sh[tid] = v;
    __syncthreads();
    for (int off = 1; off < 128; off <<= 1) {
        int t = 0;
        if (tid >= off) t = sh[tid - off];
        __syncthreads();
        if (tid >= off) sh[tid] += t;
        __syncthreads();
    }
    if (tid < NBLK) g_blockoff[tid] = sh[tid] - v;
}

__global__ void k_scan_c() {
    int i = blockIdx.x * SCAN_BLK + threadIdx.x;
    if (i < N_NODES) {
        g_rowptr[i] = g_tmp[i] + g_blockoff[blockIdx.x];
        int c = g_cnt[i];
        g_deginv[i] = 1.0f / (float)max(c, 1);
    }
    if (i == 0) g_rowptr[N_NODES] = N_EDGES;
}

__global__ void k_perm(const void* __restrict__ ei) {
    int e = blockIdx.x * blockDim.x + threadIdx.x;
    int is64 = g_is64;
    if (e < N_EDGES) {
        int s = load_idx(ei, (size_t)e, is64);
        int d = load_idx(ei, (size_t)N_EDGES + e, is64);
        int pos = g_rowptr[d] + atomicAdd(&g_cur[d], 1);
        g_perm[pos] = s;
    }
}

// ---------------- weight transpose + stack (tf32 pre-rounded) -----------------
__global__ void k_wt(const float* __restrict__ Wl, const float* __restrict__ Wr,
                     float* __restrict__ Wt) {
    int idx = blockIdx.x * blockDim.x + threadIdx.x;
    if (idx < 128 * 128) {
        int k = idx >> 7, n = idx & 127;
        Wt[n * 256 + k]       = cvt_tf32(Wl[k * 128 + n]);
        Wt[n * 256 + 128 + k] = cvt_tf32(Wr[k * 128 + n]);
    }
}

// ---------------- gather-aggregate (warp per node, lane owns 4 feats) --------
__global__ void k_gather(const float* __restrict__ feat, float* __restrict__ out) {
    int warp = (blockIdx.x * blockDim.x + threadIdx.x) >> 5;
    int lane = threadIdx.x & 31;
    if (warp >= N_NODES) return;
    int s0 = g_rowptr[warp];
    int s1 = g_rowptr[warp + 1];
    float4 acc = make_float4(0.f, 0.f, 0.f, 0.f);
    int e = s0;
    for (; e + 1 < s1; e += 2) {
        int sa = __ldg(&g_perm[e]);
        int sb = __ldg(&g_perm[e + 1]);
        float4 va = *(const float4*)(feat + (size_t)sa * DIM + lane * 4);
        float4 vb = *(const float4*)(feat + (size_t)sb * DIM + lane * 4);
        acc.x += va.x; acc.y += va.y; acc.z += va.z; acc.w += va.w;
        acc.x += vb.x; acc.y += vb.y; acc.z += vb.z; acc.w += vb.w;
    }
    if (e < s1) {
        int sa = __ldg(&g_perm[e]);
        float4 va = *(const float4*)(feat + (size_t)sa * DIM + lane * 4);
        acc.x += va.x; acc.y += va.y; acc.z += va.z; acc.w += va.w;
    }
    float di = g_deginv[warp];
    float4 o;
    o.x = cvt_tf32(acc.x * di); o.y = cvt_tf32(acc.y * di);
    o.z = cvt_tf32(acc.z * di); o.w = cvt_tf32(acc.w * di);
    *(float4*)(out + (size_t)warp * DIM + lane * 4) = o;
}

// ---------------- tf32 mma.sync GEMM with cp.async double buffering ----------
// CTA: 128(M) x 128(N). 8 warps 2x4, warp tile 64x32. K=256, 8 chunks of 32.
// fuse_pq: instead of storing the 128-wide output, project to p = h@W3l,
// q = h@W3r + b3 in the epilogue (layer-2 + layer-3 pre-projection fusion).
#define ASTRIDE 36
#define BUF_FLOATS (128 * ASTRIDE)                 // 4608 floats
#define GSM_FLOATS (4 * BUF_FLOATS + 128)
#define GSM_BYTES (GSM_FLOATS * 4)

__device__ __forceinline__ void cp16(uint32_t dst, const void* src, uint32_t srcsz) {
    asm volatile("cp.async.ca.shared.global [%0], [%1], 16, %2;"
                 :: "r"(dst), "l"(src), "r"(srcsz) : "memory");
}
__device__ __forceinline__ void cp_commit() {
    asm volatile("cp.async.commit_group;" ::: "memory");
}
template <int N>
__device__ __forceinline__ void cp_wait() {
    asm volatile("cp.async.wait_group %0;" :: "n"(N) : "memory");
}

__device__ __forceinline__ void mma_tf32(float* c, uint32_t a0, uint32_t a1,
                                         uint32_t a2, uint32_t a3,
                                         uint32_t b0, uint32_t b1) {
    asm volatile(
        "mma.sync.aligned.m16n8k8.row.col.f32.tf32.tf32.f32 "
        "{%0,%1,%2,%3}, {%4,%5,%6,%7}, {%8,%9}, {%0,%1,%2,%3};"
        : "+f"(c[0]), "+f"(c[1]), "+f"(c[2]), "+f"(c[3])
        : "r"(a0), "r"(a1), "r"(a2), "r"(a3), "r"(b0), "r"(b1));
}

__global__ void __launch_bounds__(256, 2)
k_gemm_mma(const float* __restrict__ Aagg, const float* __restrict__ Ax,
           const float* __restrict__ Wt, const float* __restrict__ bias,
           float* __restrict__ out,
           const float* __restrict__ W3l, const float* __restrict__ W3r,
           const float* __restrict__ b3,
           float* __restrict__ p_out, float* __restrict__ q_out,
           int fuse_pq) {
    extern __shared__ float sm[];
    float* Abuf = sm;                       // 2 x 128*36
    float* Bbuf = sm + 2 * BUF_FLOATS;      // 2 x 128*36
    float* sbias = sm + 4 * BUF_FLOATS;     // 128

    int tid = threadIdx.x;
    int wid = tid >> 5, lane = tid & 31;
    int g = lane >> 2, t = lane & 3;
    int warp_m = (wid >> 2) * 64;
    int warp_n = (wid & 3) * 32;
    int row_base = blockIdx.x * 128;

    if (tid < 128) sbias[tid] = bias[tid];

    uint32_t a_sm_base = (uint32_t)__cvta_generic_to_shared(Abuf);
    uint32_t b_sm_base = (uint32_t)__cvta_generic_to_shared(Bbuf);

    int lrow[4], lseg[4];
#pragma unroll
    for (int i = 0; i < 4; i++) {
        int f = tid + i * 256;
        lrow[i] = f >> 3;
        lseg[i] = f & 7;
    }

    auto issue = [&](int ch, int s) {
        int k0 = ch * 32;
        const float* Asrc = (k0 < 128) ? Aagg : Ax;
        int kbase = k0 & 127;
        uint32_t ao = a_sm_base + (uint32_t)(s * BUF_FLOATS * 4);
        uint32_t bo = b_sm_base + (uint32_t)(s * BUF_FLOATS * 4);
#pragma unroll
        for (int i = 0; i < 4; i++) {
            int row = lrow[i], seg = lseg[i];
            int gr = row_base + row;
            int ok = gr < N_NODES;
            const float* src = Asrc + (size_t)(ok ? gr : 0) * DIM + kbase + seg * 4;
            cp16(ao + (uint32_t)((row * ASTRIDE + seg * 4) * 4), src, ok ? 16u : 0u);
        }
#pragma unroll
        for (int i = 0; i < 4; i++) {
            int row = lrow[i], seg = lseg[i];
            const float* src = Wt + (size_t)row * 256 + k0 + seg * 4;
            cp16(bo + (uint32_t)((row * ASTRIDE + seg * 4) * 4), src, 16u);
        }
        cp_commit();
    };

    float acc[4][4][4];
#pragma unroll
    for (int i = 0; i < 4; i++)
#pragma unroll
        for (int j = 0; j < 4; j++)
#pragma unroll
            for (int q = 0; q < 4; q++) acc[i][j][q] = 0.f;

    issue(0, 0);

    for (int ch = 0; ch < 8; ch++) {
        int s = ch & 1;
        if (ch < 7) issue(ch + 1, s ^ 1);
        if (ch < 7) cp_wait<1>(); else cp_wait<0>();
        __syncthreads();

        const float* As = Abuf + s * BUF_FLOATS;
        const float* Bs = Bbuf + s * BUF_FLOATS;
#pragma unroll
        for (int kk = 0; kk < 4; kk++) {
            int kof = kk * 8;
            uint32_t af[4][4];
#pragma unroll
            for (int mi = 0; mi < 4; mi++) {
                const float* ap = As + (warp_m + mi * 16 + g) * ASTRIDE + kof + t;
                af[mi][0] = __float_as_uint(ap[0]);
                af[mi][1] = __float_as_uint(ap[8 * ASTRIDE]);
                af[mi][2] = __float_as_uint(ap[4]);
                af[mi][3] = __float_as_uint(ap[8 * ASTRIDE + 4]);
            }
            uint32_t bf[4][2];
#pragma unroll
            for (int ni = 0; ni < 4; ni++) {
                const float* bp = Bs + (warp_n + ni * 8 + g) * ASTRIDE + kof + t;
                bf[ni][0] = __float_as_uint(bp[0]);
                bf[ni][1] = __float_as_uint(bp[4]);
            }
#pragma unroll
            for (int mi = 0; mi < 4; mi++)
#pragma unroll
                for (int ni = 0; ni < 4; ni++)
                    mma_tf32(acc[mi][ni], af[mi][0], af[mi][1], af[mi][2], af[mi][3],
                             bf[ni][0], bf[ni][1]);
        }
        __syncthreads();
    }

    if (!fuse_pq) {
        // plain epilogue: bias + relu, direct stores
#pragma unroll
        for (int mi = 0; mi < 4; mi++) {
            int r0 = row_base + warp_m + mi * 16 + g;
            int r1 = r0 + 8;
#pragma unroll
            for (int ni = 0; ni < 4; ni++) {
                int c0 = warp_n + ni * 8 + t * 2;
                float b0 = sbias[c0], b1 = sbias[c0 + 1];
                if (r0 < N_NODES) {
                    float2 v = make_float2(fmaxf(acc[mi][ni][0] + b0, 0.f),
                                           fmaxf(acc[mi][ni][1] + b1, 0.f));
                    *(float2*)(out + (size_t)r0 * DIM + c0) = v;
                }
                if (r1 < N_NODES) {
                    float2 v = make_float2(fmaxf(acc[mi][ni][2] + b0, 0.f),
                                           fmaxf(acc[mi][ni][3] + b1, 0.f));
                    *(float2*)(out + (size_t)r1 * DIM + c0) = v;
                }
            }
        }
    } else {
        // fused epilogue: h = relu(acc + bias); p = h@W3l, q = h@W3r (+b3 later)
        // part[wid][local64][4]: overlaid on Abuf (main loop done; last sync passed)
        float* part = sm;   // 8 * 64 * 4 = 2048 floats

        // per-thread weights for its 8 columns
        float wl0[8], wl1[8], wr0[8], wr1[8], bcol[8];
#pragma unroll
        for (int ni = 0; ni < 4; ni++) {
#pragma unroll
            for (int cc = 0; cc < 2; cc++) {
                int j = ni * 2 + cc;
                int c = warp_n + ni * 8 + t * 2 + cc;
                wl0[j] = __ldg(&W3l[c * 2 + 0]);
                wl1[j] = __ldg(&W3l[c * 2 + 1]);
                wr0[j] = __ldg(&W3r[c * 2 + 0]);
                wr1[j] = __ldg(&W3r[c * 2 + 1]);
                bcol[j] = sbias[c];
            }
        }

#pragma unroll
        for (int mi = 0; mi < 4; mi++) {
            float s0p0 = 0.f, s0p1 = 0.f, s0q0 = 0.f, s0q1 = 0.f;
            float s1p0 = 0.f, s1p1 = 0.f, s1q0 = 0.f, s1q1 = 0.f;
#pragma unroll
            for (int ni = 0; ni < 4; ni++) {
                int j0 = ni * 2, j1 = ni * 2 + 1;
                float v0 = fmaxf(acc[mi][ni][0] + bcol[j0], 0.f);   // r0, col j0
                float v1 = fmaxf(acc[mi][ni][1] + bcol[j1], 0.f);   // r0, col j1
                float v2 = fmaxf(acc[mi][ni][2] + bcol[j0], 0.f);   // r1, col j0
                float v3 = fmaxf(acc[mi][ni][3] + bcol[j1], 0.f);   // r1, col j1
                s0p0 = fmaf(v0, wl0[j0], fmaf(v1, wl0[j1], s0p0));
                s0p1 = fmaf(v0, wl1[j0], fmaf(v1, wl1[j1], s0p1));
                s0q0 = fmaf(v0, wr0[j0], fmaf(v1, wr0[j1], s0q0));
                s0q1 = fmaf(v0, wr1[j0], fmaf(v1, wr1[j1], s0q1));
                s1p0 = fmaf(v2, wl0[j0], fmaf(v3, wl0[j1], s1p0));
                s1p1 = fmaf(v2, wl1[j0], fmaf(v3, wl1[j1], s1p1));
                s1q0 = fmaf(v2, wr0[j0], fmaf(v3, wr0[j1], s1q0));
                s1q1 = fmaf(v2, wr1[j0], fmaf(v3, wr1[j1], s1q1));
            }
            // reduce over t (4 lanes within g-group)
#pragma unroll
            for (int off = 1; off < 4; off <<= 1) {
                s0p0 += __shfl_down_sync(0xffffffffu, s0p0, off, 4);
                s0p1 += __shfl_down_sync(0xffffffffu, s0p1, off, 4);
                s0q0 += __shfl_down_sync(0xffffffffu, s0q0, off, 4);
                s0q1 += __shfl_down_sync(0xffffffffu, s0q1, off, 4);
                s1p0 += __shfl_down_sync(0xffffffffu, s1p0, off, 4);
                s1p1 += __shfl_down_sync(0xffffffffu, s1p1, off, 4);
                s1q0 += __shfl_down_sync(0xffffffffu, s1q0, off, 4);
                s1q1 += __shfl_down_sync(0xffffffffu, s1q1, off, 4);
            }
            if (t == 0) {
                int l0 = mi * 16 + g;
                float* pr0 = part + (wid * 64 + l0) * 4;
                pr0[0] = s0p0; pr0[1] = s0p1; pr0[2] = s0q0; pr0[3] = s0q1;
                float* pr1 = part + (wid * 64 + l0 + 8) * 4;
                pr1[0] = s1p0; pr1[1] = s1p1; pr1[2] = s1q0; pr1[3] = s1q1;
            }
        }
        __syncthreads();

        // cross-warp reduce: 128 rows x 4 vals, 4 n-warps per m-group
        for (int idx = tid; idx < 512; idx += 256) {
            int rl = idx >> 2, v = idx & 3;
            int grp = rl >> 6;            // warp_m group
            int l64 = rl & 63;
            float s = 0.f;
#pragma unroll
            for (int w = 0; w < 4; w++)
                s += part[((grp * 4 + w) * 64 + l64) * 4 + v];
            int node = row_base + rl;
            if (node < N_NODES) {
                if (v < 2) p_out[node * 2 + v] = s;
                else       q_out[node * 2 + (v - 2)] = s + __ldg(&b3[v - 2]);
            }
        }
    }
}

// ---------------- layer-3 gather + relu + log_softmax ------------------------
__global__ void k_final(float* __restrict__ out) {
    int warp = (blockIdx.x * blockDim.x + threadIdx.x) >> 5;
    int lane = threadIdx.x & 31;
    if (warp >= N_NODES) return;
    int s0 = g_rowptr[warp];
    int s1 = g_rowptr[warp + 1];
    float a0 = 0.f, a1 = 0.f;
    for (int e = s0 + lane; e < s1; e += 32) {
        int s = __ldg(&g_perm[e]);
        a0 += g_p[s * 2 + 0];
        a1 += g_p[s * 2 + 1];
    }
#pragma unroll
    for (int off = 16; off > 0; off >>= 1) {
        a0 += __shfl_down_sync(0xffffffffu, a0, off);
        a1 += __shfl_down_sync(0xffffffffu, a1, off);
    }
    if (lane == 0) {
        float di = g_deginv[warp];
        float v0 = fmaxf(a0 * di + g_q[warp * 2 + 0], 0.f);
        float v1 = fmaxf(a1 * di + g_q[warp * 2 + 1], 0.f);
        float m = fmaxf(v0, v1);
        float lse = m + logf(expf(v0 - m) + expf(v1 - m));
        out[warp * 2 + 0] = v0 - lse;
        out[warp * 2 + 1] = v1 - lse;
    }
}

// ---------------- launch -----------------------------------------------------
extern "C" void kernel_launch(void* const* d_in, const int* in_sizes, int n_in,
                              void* d_out, int out_size) {
    const float* x   = (const float*)d_in[0];
    const void*  ei  = d_in[1];
    const float* W1l = (const float*)d_in[2];
    const float* W1r = (const float*)d_in[3];
    const float* b1  = (const float*)d_in[4];
    const float* W2l = (const float*)d_in[5];
    const float* W2r = (const float*)d_in[6];
    const float* b2  = (const float*)d_in[7];
    const float* W3l = (const float*)d_in[8];
    const float* W3r = (const float*)d_in[9];
    const float* b3  = (const float*)d_in[10];
    float* out = (float*)d_out;

    const int EDGE_BLOCKS = (N_EDGES + 255) / 256;
    const int NODE_BLOCKS = (N_NODES + 255) / 256;
    const int WARP_BLOCKS = (N_NODES * 32 + 255) / 256;
    const int GEMM_BLOCKS = (N_NODES + 127) / 128;     // 782

    float* agg; cudaGetSymbolAddress((void**)&agg, g_agg);
    float* h1;  cudaGetSymbolAddress((void**)&h1,  g_h1);
    float* wt1; cudaGetSymbolAddress((void**)&wt1, g_wt1);
    float* wt2; cudaGetSymbolAddress((void**)&wt2, g_wt2);
    float* p;   cudaGetSymbolAddress((void**)&p,   g_p);
    float* q;   cudaGetSymbolAddress((void**)&q,   g_q);

    cudaFuncSetAttribute(k_gemm_mma, cudaFuncAttributeMaxDynamicSharedMemorySize, GSM_BYTES);

    // CSR build (block 0 of k_zero_counts sniffs dtype) + weight prep
    k_zero_counts<<<NODE_BLOCKS, 256>>>((const int*)ei);
    k_hist<<<EDGE_BLOCKS, 256>>>(ei);
    k_scan_a<<<NBLK, SCAN_BLK>>>();
    k_scan_b<<<1, 128>>>();
    k_scan_c<<<NBLK, SCAN_BLK>>>();
    k_perm<<<EDGE_BLOCKS, 256>>>(ei);
    k_wt<<<(128 * 128 + 255) / 256, 256>>>(W1l, W1r, wt1);
    k_wt<<<(128 * 128 + 255) / 256, 256>>>(W2l, W2r, wt2);

    // layer 1
    k_gather<<<WARP_BLOCKS, 256>>>(x, agg);
    k_gemm_mma<<<GEMM_BLOCKS, 256, GSM_BYTES>>>(agg, x, wt1, b1, h1,
                                                W3l, W3r, b3, p, q, 0);

    // layer 2 + layer-3 projection fused into the GEMM epilogue
    k_gather<<<WARP_BLOCKS, 256>>>(h1, agg);
    k_gemm_mma<<<GEMM_BLOCKS, 256, GSM_BYTES>>>(agg, h1, wt2, b2, h1,
                                                W3l, W3r, b3, p, q, 1);

    // layer 3 aggregation + log_softmax
    k_final<<<WARP_BLOCKS, 256>>>(out);
}